// round 6
// baseline (speedup 1.0000x reference)
#include <cuda_runtime.h>
#include <cuda_bf16.h>
#include <cstdint>

// ---------------------------------------------------------------------------
// Problem constants
// ---------------------------------------------------------------------------
#define LQ      22223
#define CDIM    256
#define NHEADS  8
#define NLVL    4
#define NPTS    4
#define KDIM    256

__device__ __constant__ int c_H[NLVL]     = {100, 50, 25, 13};
__device__ __constant__ int c_W[NLVL]     = {167, 84, 42, 21};
__device__ __constant__ int c_start[NLVL] = {0, 16700, 20900, 21950};

// ---------------------------------------------------------------------------
// Scratch (device globals; no allocation allowed)
// ---------------------------------------------------------------------------
__device__ float g_v   [LQ * CDIM];   // value @ W_val + b_val
__device__ float g_oa  [LQ * 384];    // [off(256) | attn logits(128)] per row
__device__ float g_mid [LQ * CDIM];   // sampled output, pre-W_out

// Weight splits, transposed to [N,K], packed: WVAL | WOFF | WATTN | WOUT
// (WOFF and WATTN adjacent -> one combined N=384 GEMM for query)
#define W_VAL_OFF   0
#define W_OFF_OFF   (256 * 256)
#define W_ATTN_OFF  (2 * 256 * 256)
#define W_OUT_OFF   (2 * 256 * 256 + 128 * 256)
#define W_TOTAL     (3 * 256 * 256 + 128 * 256)
__device__ __nv_bfloat16 g_wh[W_TOTAL];
__device__ __nv_bfloat16 g_wl[W_TOTAL];

// ---------------------------------------------------------------------------
// mma.sync / ldmatrix helpers (plain sm_103)
// ---------------------------------------------------------------------------
__device__ __forceinline__ uint32_t smem_u32(const void* p) {
    uint32_t a;
    asm("{ .reg .u64 t; cvta.to.shared.u64 t, %1; cvt.u32.u64 %0, t; }"
        : "=r"(a) : "l"(p));
    return a;
}
__device__ __forceinline__ void ldsm_x4(uint32_t* r, uint32_t addr) {
    asm volatile("ldmatrix.sync.aligned.m8n8.x4.shared.b16 {%0,%1,%2,%3}, [%4];"
                 : "=r"(r[0]), "=r"(r[1]), "=r"(r[2]), "=r"(r[3]) : "r"(addr));
}
__device__ __forceinline__ void mma_bf16(float* d, const uint32_t* a,
                                         const uint32_t* b) {
    asm volatile(
        "mma.sync.aligned.m16n8k16.row.col.f32.bf16.bf16.f32 "
        "{%0,%1,%2,%3}, {%4,%5,%6,%7}, {%8,%9}, {%0,%1,%2,%3};"
        : "+f"(d[0]), "+f"(d[1]), "+f"(d[2]), "+f"(d[3])
        : "r"(a[0]), "r"(a[1]), "r"(a[2]), "r"(a[3]), "r"(b[0]), "r"(b[1]));
}

// ---------------------------------------------------------------------------
// Fused weight prep: split all four fp32 W[K,N] into bf16 hi/lo at [N,K].
// ---------------------------------------------------------------------------
__global__ void prep_all_w(const float* __restrict__ Wv,
                           const float* __restrict__ Wo,
                           const float* __restrict__ Wa,
                           const float* __restrict__ Wu,
                           __nv_bfloat16* __restrict__ wh,
                           __nv_bfloat16* __restrict__ wl)
{
    int i = blockIdx.x * blockDim.x + threadIdx.x;
    if (i >= W_TOTAL) return;
    const float* W;
    int N, local, base;
    if (i < 65536)        { W = Wv; N = 256; base = W_VAL_OFF;  local = i; }
    else if (i < 131072)  { W = Wo; N = 256; base = W_OFF_OFF;  local = i - 65536; }
    else if (i < 163840)  { W = Wa; N = 128; base = W_ATTN_OFF; local = i - 131072; }
    else                  { W = Wu; N = 256; base = W_OUT_OFF;  local = i - 163840; }
    int k = local / N;
    int n = local - k * N;
    float a = W[(size_t)k * N + n];
    __nv_bfloat16 hi = __float2bfloat16(a);
    __nv_bfloat16 lo = __float2bfloat16(a - __bfloat162float(hi));
    wh[(size_t)base + (size_t)n * KDIM + k] = hi;
    wl[(size_t)base + (size_t)n * KDIM + k] = lo;
}

// ---------------------------------------------------------------------------
// K-resident split-bf16 mma.sync GEMM.
// C[M,N] = A_fp32[M,256] @ B[256,N] + bias  (B as [N,K] bf16 hi/lo)
// BM=128, BN=64, K=256 resident. 512 threads / 16 warps, warp tile 32x16.
// bias: col < nsplit -> bias0[col], else bias1[col - nsplit].
// ---------------------------------------------------------------------------
#define LDK 264
#define SM_AH 0
#define SM_AL (128 * LDK * 2)
#define SM_BH (2 * 128 * LDK * 2)
#define SM_BL (SM_BH + 64 * LDK * 2)
#define SM_TOTAL (SM_BL + 64 * LDK * 2)   // 202752

__global__ __launch_bounds__(512)
void gemm_kres(const float* __restrict__ A,
               const __nv_bfloat16* __restrict__ bh,
               const __nv_bfloat16* __restrict__ bl,
               const float* __restrict__ bias0,
               const float* __restrict__ bias1,
               int nsplit,
               float* __restrict__ C,
               int M, int N)
{
    extern __shared__ __align__(16) char smem[];
    __nv_bfloat16* Ah = reinterpret_cast<__nv_bfloat16*>(smem + SM_AH);
    __nv_bfloat16* Al = reinterpret_cast<__nv_bfloat16*>(smem + SM_AL);
    __nv_bfloat16* Bh = reinterpret_cast<__nv_bfloat16*>(smem + SM_BH);
    __nv_bfloat16* Bl = reinterpret_cast<__nv_bfloat16*>(smem + SM_BL);

    const int tid  = threadIdx.x;
    const int wid  = tid >> 5;
    const int lane = tid & 31;
    const int m0   = blockIdx.x * 128;
    const int col0 = blockIdx.y * 64;
    const int warp_m = wid & 3;     // 32 rows each
    const int warp_n = wid >> 2;    // 0..3, 16 cols each

    // ---- load A (fp32) and split to hi/lo bf16 in SMEM ----
    {
        const int r  = tid >> 2;              // 0..127, 4 threads per row
        const int cb = (tid & 3) * 64;        // quarter-row base
        const int gr = m0 + r;
        #pragma unroll
        for (int j = 0; j < 16; j++) {        // 16 float4 per quarter-row
            const int c4 = cb + j * 4;
            float4 v = make_float4(0.f, 0.f, 0.f, 0.f);
            if (gr < M)
                v = *reinterpret_cast<const float4*>(&A[(size_t)gr * KDIM + c4]);
            __nv_bfloat162 h01 = __floats2bfloat162_rn(v.x, v.y);
            __nv_bfloat162 h23 = __floats2bfloat162_rn(v.z, v.w);
            __nv_bfloat162 l01 = __floats2bfloat162_rn(
                v.x - __bfloat162float(h01.x), v.y - __bfloat162float(h01.y));
            __nv_bfloat162 l23 = __floats2bfloat162_rn(
                v.z - __bfloat162float(h23.x), v.w - __bfloat162float(h23.y));
            const int o = r * LDK + c4;
            *reinterpret_cast<__nv_bfloat162*>(&Ah[o])     = h01;
            *reinterpret_cast<__nv_bfloat162*>(&Ah[o + 2]) = h23;
            *reinterpret_cast<__nv_bfloat162*>(&Al[o])     = l01;
            *reinterpret_cast<__nv_bfloat162*>(&Al[o + 2]) = l23;
        }
    }
    // ---- load B hi/lo (bf16 [N,K]) ----
    #pragma unroll
    for (int i = 0; i < 4; i++) {
        const int idx = tid + (i << 9);
        const int r  = idx >> 5;              // 0..63
        const int c8 = (idx & 31) << 3;       // 0..248
        const size_t g = (size_t)(col0 + r) * KDIM + c8;
        const int o = r * LDK + c8;
        *reinterpret_cast<uint4*>(&Bh[o]) = *reinterpret_cast<const uint4*>(&bh[g]);
        *reinterpret_cast<uint4*>(&Bl[o]) = *reinterpret_cast<const uint4*>(&bl[g]);
    }
    __syncthreads();

    // ---- MMA: 16 K-steps x 3 split-products, no barriers ----
    float acc[2][2][4];
    #pragma unroll
    for (int i = 0; i < 2; i++)
        #pragma unroll
        for (int j = 0; j < 2; j++)
            #pragma unroll
            for (int k = 0; k < 4; k++) acc[i][j][k] = 0.0f;

    const uint32_t sAh = smem_u32(Ah), sAl = smem_u32(Al);
    const uint32_t sBh = smem_u32(Bh), sBl = smem_u32(Bl);
    const int a_row  = warp_m * 32 + (lane & 15);
    const int a_colb = (lane >> 4) << 3;
    const int b_row  = warp_n * 16 + (lane & 7) + ((lane >> 4) << 3);
    const int b_colb = ((lane >> 3) & 1) << 3;

    #pragma unroll
    for (int ks = 0; ks < 16; ks++) {
        const int kc = ks << 4;
        uint32_t fah[2][4], fal[2][4], fbh[4], fbl[4];
        #pragma unroll
        for (int mt = 0; mt < 2; mt++) {
            const uint32_t off = (uint32_t)(((a_row + mt * 16) * LDK + kc + a_colb) * 2);
            ldsm_x4(fah[mt], sAh + off);
            ldsm_x4(fal[mt], sAl + off);
        }
        {
            const uint32_t off = (uint32_t)((b_row * LDK + kc + b_colb) * 2);
            ldsm_x4(fbh, sBh + off);
            ldsm_x4(fbl, sBl + off);
        }
        #pragma unroll
        for (int mt = 0; mt < 2; mt++)
            #pragma unroll
            for (int nt = 0; nt < 2; nt++)
                mma_bf16(acc[mt][nt], fah[mt], &fbh[nt * 2]);
        #pragma unroll
        for (int mt = 0; mt < 2; mt++)
            #pragma unroll
            for (int nt = 0; nt < 2; nt++)
                mma_bf16(acc[mt][nt], fah[mt], &fbl[nt * 2]);
        #pragma unroll
        for (int mt = 0; mt < 2; mt++)
            #pragma unroll
            for (int nt = 0; nt < 2; nt++)
                mma_bf16(acc[mt][nt], fal[mt], &fbh[nt * 2]);
    }

    // ---- epilogue ----
    const int er = lane >> 2;
    const int ec = (lane & 3) << 1;
    #pragma unroll
    for (int mt = 0; mt < 2; mt++) {
        #pragma unroll
        for (int nt = 0; nt < 2; nt++) {
            const int col = col0 + warp_n * 16 + nt * 8 + ec;
            const float b0 = (col < nsplit)     ? bias0[col]     : bias1[col - nsplit];
            const float b1 = (col + 1 < nsplit) ? bias0[col + 1] : bias1[col + 1 - nsplit];
            const int r0 = m0 + warp_m * 32 + mt * 16 + er;
            if (r0 < M) {
                float2 o = make_float2(acc[mt][nt][0] + b0, acc[mt][nt][1] + b1);
                *reinterpret_cast<float2*>(&C[(size_t)r0 * N + col]) = o;
            }
            if (r0 + 8 < M) {
                float2 o = make_float2(acc[mt][nt][2] + b0, acc[mt][nt][3] + b1);
                *reinterpret_cast<float2*>(&C[(size_t)(r0 + 8) * N + col]) = o;
            }
        }
    }
}

// ---------------------------------------------------------------------------
// Deformable sampling with fused softmax: one warp per (q, head), lane=channel.
// off/logits packed in g_oa rows of 384: [off 256 | logits 128].
// ---------------------------------------------------------------------------
__global__ __launch_bounds__(256) void sample_kernel(
    const float* __restrict__ v, const float* __restrict__ oa,
    const float* __restrict__ ref, float* __restrict__ mid)
{
    const int q    = blockIdx.x;
    const int h    = threadIdx.x >> 5;
    const int lane = threadIdx.x & 31;

    float lg = oa[(size_t)q * 384 + 256 + h * 16 + (lane & 15)];
    float mx = lg;
    #pragma unroll
    for (int m = 8; m; m >>= 1) mx = fmaxf(mx, __shfl_xor_sync(~0u, mx, m));
    float ex = __expf(lg - mx);
    float sm = ex;
    #pragma unroll
    for (int m = 8; m; m >>= 1) sm += __shfl_xor_sync(~0u, sm, m);
    const float wn = ex / sm;

    const float* offq = oa + (size_t)q * 384 + h * 32;
    const float* refq = ref + (size_t)q * 16;

    float acc = 0.0f;

    #pragma unroll
    for (int l = 0; l < NLVL; l++) {
        const float cx = refq[l * 4 + 0];
        const float cy = refq[l * 4 + 1];
        const float rw = refq[l * 4 + 2];
        const float rh = refq[l * 4 + 3];
        const int H = c_H[l], W = c_W[l];
        const int start = c_start[l];
        const float* vbase = v + ((size_t)start * CDIM) + h * 32 + lane;

        #pragma unroll
        for (int p = 0; p < NPTS; p++) {
            const float ox = offq[l * 8 + p * 2 + 0];
            const float oy = offq[l * 8 + p * 2 + 1];
            const float x = (cx + ox * 0.125f * rw) * (float)W - 0.5f;
            const float y = (cy + oy * 0.125f * rh) * (float)H - 0.5f;

            const float x0f = floorf(x), y0f = floorf(y);
            const int x0 = (int)x0f, y0 = (int)y0f;
            const float wx1 = x - x0f, wy1 = y - y0f;
            const float wx0 = 1.0f - wx1, wy0 = 1.0f - wy1;

            const bool vx0 = (x0 >= 0) && (x0 < W);
            const bool vx1 = (x0 + 1 >= 0) && (x0 + 1 < W);
            const bool vy0 = (y0 >= 0) && (y0 < H);
            const bool vy1 = (y0 + 1 >= 0) && (y0 + 1 < H);

            float s = 0.0f;
            if (vy0) {
                const float* rowp = vbase + (size_t)y0 * W * CDIM;
                if (vx0) s = fmaf(wy0 * wx0, rowp[(size_t)x0 * CDIM], s);
                if (vx1) s = fmaf(wy0 * wx1, rowp[(size_t)(x0 + 1) * CDIM], s);
            }
            if (vy1) {
                const float* rowp = vbase + (size_t)(y0 + 1) * W * CDIM;
                if (vx0) s = fmaf(wy1 * wx0, rowp[(size_t)x0 * CDIM], s);
                if (vx1) s = fmaf(wy1 * wx1, rowp[(size_t)(x0 + 1) * CDIM], s);
            }
            const float aw = __shfl_sync(~0u, wn, (l * 4 + p) | (lane & 16));
            acc = fmaf(aw, s, acc);
        }
    }

    mid[(size_t)q * CDIM + h * 32 + lane] = acc;
}

// ---------------------------------------------------------------------------
// Launch
// ---------------------------------------------------------------------------
extern "C" void kernel_launch(void* const* d_in, const int* in_sizes, int n_in,
                              void* d_out, int out_size)
{
    const float* query  = (const float*)d_in[0];
    const float* ref    = (const float*)d_in[1];
    const float* value  = (const float*)d_in[2];
    const float* W_off  = (const float*)d_in[3];
    const float* b_off  = (const float*)d_in[4];
    const float* W_attn = (const float*)d_in[5];
    const float* b_attn = (const float*)d_in[6];
    const float* W_val  = (const float*)d_in[7];
    const float* b_val  = (const float*)d_in[8];
    const float* W_out  = (const float*)d_in[9];
    const float* b_out  = (const float*)d_in[10];
    float* out = (float*)d_out;

    float *gv, *goa, *gmid;
    __nv_bfloat16 *wh, *wl;
    cudaGetSymbolAddress((void**)&gv,   g_v);
    cudaGetSymbolAddress((void**)&goa,  g_oa);
    cudaGetSymbolAddress((void**)&gmid, g_mid);
    cudaGetSymbolAddress((void**)&wh,   g_wh);
    cudaGetSymbolAddress((void**)&wl,   g_wl);

    cudaFuncSetAttribute(gemm_kres, cudaFuncAttributeMaxDynamicSharedMemorySize,
                         SM_TOTAL);

    const int MT = (LQ + 127) / 128;   // 174
    dim3 gv256(MT, 4);                 // N=256
    dim3 gq384(MT, 6);                 // N=384 (off | attn)

    // 0. weight prep
    prep_all_w<<<(W_TOTAL + 255) / 256, 256>>>(W_val, W_off, W_attn, W_out, wh, wl);

    // 1. v = value @ W_val + b_val
    gemm_kres<<<gv256, 512, SM_TOTAL>>>(value, wh + W_VAL_OFF, wl + W_VAL_OFF,
                                        b_val, b_val, 1 << 30, gv, LQ, 256);
    // 2. [off | attn] = query @ [W_off | W_attn]
    gemm_kres<<<gq384, 512, SM_TOTAL>>>(query, wh + W_OFF_OFF, wl + W_OFF_OFF,
                                        b_off, b_attn, 256, goa, LQ, 384);
    // 3. sampling (softmax fused)
    sample_kernel<<<LQ, 256>>>(gv, goa, ref, gmid);
    // 4. out = mid @ W_out + b_out
    gemm_kres<<<gv256, 512, SM_TOTAL>>>(gmid, wh + W_OUT_OFF, wl + W_OUT_OFF,
                                        b_out, b_out, 1 << 30, out, LQ, 256);
}

// round 7
// speedup vs baseline: 1.5433x; 1.5433x over previous
#include <cuda_runtime.h>
#include <cuda_bf16.h>
#include <cstdint>

// ---------------------------------------------------------------------------
// Problem constants
// ---------------------------------------------------------------------------
#define LQ      22223
#define CDIM    256
#define NHEADS  8
#define NLVL    4
#define NPTS    4
#define KDIM    256

__device__ __constant__ int c_H[NLVL]     = {100, 50, 25, 13};
__device__ __constant__ int c_W[NLVL]     = {167, 84, 42, 21};
__device__ __constant__ int c_start[NLVL] = {0, 16700, 20900, 21950};

// ---------------------------------------------------------------------------
// Scratch (device globals; no allocation allowed)
// ---------------------------------------------------------------------------
__device__ float g_v   [LQ * CDIM];   // value @ W_val + b_val
__device__ float g_oa  [LQ * 384];    // [off(256) | attn logits(128)] per row
__device__ float g_mid [LQ * CDIM];   // sampled output, pre-W_out

// Weight splits, transposed to [N,K], packed: WVAL | WOFF | WATTN | WOUT
#define W_VAL_OFF   0
#define W_OFF_OFF   (256 * 256)
#define W_ATTN_OFF  (2 * 256 * 256)
#define W_OUT_OFF   (2 * 256 * 256 + 128 * 256)
#define W_TOTAL     (3 * 256 * 256 + 128 * 256)
__device__ __nv_bfloat16 g_wh[W_TOTAL];
__device__ __nv_bfloat16 g_wl[W_TOTAL];

// ---------------------------------------------------------------------------
// mma.sync / ldmatrix helpers (plain sm_103)
// ---------------------------------------------------------------------------
__device__ __forceinline__ uint32_t smem_u32(const void* p) {
    uint32_t a;
    asm("{ .reg .u64 t; cvta.to.shared.u64 t, %1; cvt.u32.u64 %0, t; }"
        : "=r"(a) : "l"(p));
    return a;
}
__device__ __forceinline__ void ldsm_x4(uint32_t* r, uint32_t addr) {
    asm volatile("ldmatrix.sync.aligned.m8n8.x4.shared.b16 {%0,%1,%2,%3}, [%4];"
                 : "=r"(r[0]), "=r"(r[1]), "=r"(r[2]), "=r"(r[3]) : "r"(addr));
}
__device__ __forceinline__ void mma_bf16(float* d, const uint32_t* a,
                                         const uint32_t* b) {
    asm volatile(
        "mma.sync.aligned.m16n8k16.row.col.f32.bf16.bf16.f32 "
        "{%0,%1,%2,%3}, {%4,%5,%6,%7}, {%8,%9}, {%0,%1,%2,%3};"
        : "+f"(d[0]), "+f"(d[1]), "+f"(d[2]), "+f"(d[3])
        : "r"(a[0]), "r"(a[1]), "r"(a[2]), "r"(a[3]), "r"(b[0]), "r"(b[1]));
}

// ---------------------------------------------------------------------------
// Fused weight prep
// ---------------------------------------------------------------------------
__global__ void prep_all_w(const float* __restrict__ Wv,
                           const float* __restrict__ Wo,
                           const float* __restrict__ Wa,
                           const float* __restrict__ Wu,
                           __nv_bfloat16* __restrict__ wh,
                           __nv_bfloat16* __restrict__ wl)
{
    int i = blockIdx.x * blockDim.x + threadIdx.x;
    if (i >= W_TOTAL) return;
    const float* W;
    int N, local, base;
    if (i < 65536)        { W = Wv; N = 256; base = W_VAL_OFF;  local = i; }
    else if (i < 131072)  { W = Wo; N = 256; base = W_OFF_OFF;  local = i - 65536; }
    else if (i < 163840)  { W = Wa; N = 128; base = W_ATTN_OFF; local = i - 131072; }
    else                  { W = Wu; N = 256; base = W_OUT_OFF;  local = i - 163840; }
    int k = local / N;
    int n = local - k * N;
    float a = W[(size_t)k * N + n];
    __nv_bfloat16 hi = __float2bfloat16(a);
    __nv_bfloat16 lo = __float2bfloat16(a - __bfloat162float(hi));
    wh[(size_t)base + (size_t)n * KDIM + k] = hi;
    wl[(size_t)base + (size_t)n * KDIM + k] = lo;
}

// ---------------------------------------------------------------------------
// K-resident split-bf16 mma.sync GEMM (round-5 proven shape: 256 thr, 8 warps,
// warp tile 32x32). bias split for merged outputs.
// ---------------------------------------------------------------------------
#define LDK 264
#define SM_AH 0
#define SM_AL (128 * LDK * 2)
#define SM_BH (2 * 128 * LDK * 2)
#define SM_BL (SM_BH + 64 * LDK * 2)
#define SM_TOTAL (SM_BL + 64 * LDK * 2)   // 202752

__global__ __launch_bounds__(256)
void gemm_kres(const float* __restrict__ A,
               const __nv_bfloat16* __restrict__ bh,
               const __nv_bfloat16* __restrict__ bl,
               const float* __restrict__ bias0,
               const float* __restrict__ bias1,
               int nsplit,
               float* __restrict__ C,
               int M, int N)
{
    extern __shared__ __align__(16) char smem[];
    __nv_bfloat16* Ah = reinterpret_cast<__nv_bfloat16*>(smem + SM_AH);
    __nv_bfloat16* Al = reinterpret_cast<__nv_bfloat16*>(smem + SM_AL);
    __nv_bfloat16* Bh = reinterpret_cast<__nv_bfloat16*>(smem + SM_BH);
    __nv_bfloat16* Bl = reinterpret_cast<__nv_bfloat16*>(smem + SM_BL);

    const int tid  = threadIdx.x;
    const int wid  = tid >> 5;
    const int lane = tid & 31;
    const int m0   = blockIdx.x * 128;
    const int col0 = blockIdx.y * 64;
    const int warp_m = wid & 3;
    const int warp_n = wid >> 2;

    // ---- load A (fp32) and split to hi/lo bf16 in SMEM ----
    {
        const int r  = tid >> 1;
        const int cb = (tid & 1) * 128;
        const int gr = m0 + r;
        #pragma unroll
        for (int j = 0; j < 32; j++) {
            const int c4 = cb + j * 4;
            float4 v = make_float4(0.f, 0.f, 0.f, 0.f);
            if (gr < M)
                v = *reinterpret_cast<const float4*>(&A[(size_t)gr * KDIM + c4]);
            __nv_bfloat162 h01 = __floats2bfloat162_rn(v.x, v.y);
            __nv_bfloat162 h23 = __floats2bfloat162_rn(v.z, v.w);
            __nv_bfloat162 l01 = __floats2bfloat162_rn(
                v.x - __bfloat162float(h01.x), v.y - __bfloat162float(h01.y));
            __nv_bfloat162 l23 = __floats2bfloat162_rn(
                v.z - __bfloat162float(h23.x), v.w - __bfloat162float(h23.y));
            const int o = r * LDK + c4;
            *reinterpret_cast<__nv_bfloat162*>(&Ah[o])     = h01;
            *reinterpret_cast<__nv_bfloat162*>(&Ah[o + 2]) = h23;
            *reinterpret_cast<__nv_bfloat162*>(&Al[o])     = l01;
            *reinterpret_cast<__nv_bfloat162*>(&Al[o + 2]) = l23;
        }
    }
    // ---- load B hi/lo ----
    #pragma unroll
    for (int i = 0; i < 8; i++) {
        const int idx = tid + (i << 8);
        const int r  = idx >> 5;
        const int c8 = (idx & 31) << 3;
        const size_t g = (size_t)(col0 + r) * KDIM + c8;
        const int o = r * LDK + c8;
        *reinterpret_cast<uint4*>(&Bh[o]) = *reinterpret_cast<const uint4*>(&bh[g]);
        *reinterpret_cast<uint4*>(&Bl[o]) = *reinterpret_cast<const uint4*>(&bl[g]);
    }
    __syncthreads();

    float acc[2][4][4];
    #pragma unroll
    for (int i = 0; i < 2; i++)
        #pragma unroll
        for (int j = 0; j < 4; j++)
            #pragma unroll
            for (int k = 0; k < 4; k++) acc[i][j][k] = 0.0f;

    const uint32_t sAh = smem_u32(Ah), sAl = smem_u32(Al);
    const uint32_t sBh = smem_u32(Bh), sBl = smem_u32(Bl);
    const int a_row  = warp_m * 32 + (lane & 15);
    const int a_colb = (lane >> 4) << 3;
    const int b_row  = warp_n * 32 + (lane & 7) + ((lane >> 4) << 3);
    const int b_colb = ((lane >> 3) & 1) << 3;

    #pragma unroll
    for (int ks = 0; ks < 16; ks++) {
        const int kc = ks << 4;
        uint32_t fah[2][4], fal[2][4], fbh[2][4], fbl[2][4];
        #pragma unroll
        for (int mt = 0; mt < 2; mt++) {
            const uint32_t off = (uint32_t)(((a_row + mt * 16) * LDK + kc + a_colb) * 2);
            ldsm_x4(fah[mt], sAh + off);
            ldsm_x4(fal[mt], sAl + off);
        }
        #pragma unroll
        for (int np = 0; np < 2; np++) {
            const uint32_t off = (uint32_t)(((b_row + np * 16) * LDK + kc + b_colb) * 2);
            ldsm_x4(fbh[np], sBh + off);
            ldsm_x4(fbl[np], sBl + off);
        }
        #pragma unroll
        for (int mt = 0; mt < 2; mt++)
            #pragma unroll
            for (int nt = 0; nt < 4; nt++)
                mma_bf16(acc[mt][nt], fah[mt], &fbh[nt >> 1][(nt & 1) * 2]);
        #pragma unroll
        for (int mt = 0; mt < 2; mt++)
            #pragma unroll
            for (int nt = 0; nt < 4; nt++)
                mma_bf16(acc[mt][nt], fah[mt], &fbl[nt >> 1][(nt & 1) * 2]);
        #pragma unroll
        for (int mt = 0; mt < 2; mt++)
            #pragma unroll
            for (int nt = 0; nt < 4; nt++)
                mma_bf16(acc[mt][nt], fal[mt], &fbh[nt >> 1][(nt & 1) * 2]);
    }

    const int er = lane >> 2;
    const int ec = (lane & 3) << 1;
    #pragma unroll
    for (int mt = 0; mt < 2; mt++) {
        #pragma unroll
        for (int nt = 0; nt < 4; nt++) {
            const int col = col0 + warp_n * 32 + nt * 8 + ec;
            const float b0 = (col < nsplit)     ? bias0[col]     : bias1[col - nsplit];
            const float b1 = (col + 1 < nsplit) ? bias0[col + 1] : bias1[col + 1 - nsplit];
            const int r0 = m0 + warp_m * 32 + mt * 16 + er;
            if (r0 < M) {
                float2 o = make_float2(acc[mt][nt][0] + b0, acc[mt][nt][1] + b1);
                *reinterpret_cast<float2*>(&C[(size_t)r0 * N + col]) = o;
            }
            if (r0 + 8 < M) {
                float2 o = make_float2(acc[mt][nt][2] + b0, acc[mt][nt][3] + b1);
                *reinterpret_cast<float2*>(&C[(size_t)(r0 + 8) * N + col]) = o;
            }
        }
    }
}

// ---------------------------------------------------------------------------
// Sampling v2: precompute phase (128 threads: one per (h,l,p) point) +
// gather phase (8 warps: warp=head, lane=(corner-group, channel-quad)).
// Per point per lane: 2 scalar LDS (broadcast) + 1 LDG.128 + 4 FFMA.
// ---------------------------------------------------------------------------
__global__ __launch_bounds__(256) void sample_kernel(
    const float* __restrict__ v, const float* __restrict__ oa,
    const float* __restrict__ ref, float* __restrict__ mid)
{
    __shared__ int   s_off[128 * 4];   // [h*16+pt][corner] element offset (h*32 folded)
    __shared__ float s_w  [128 * 4];   // bilinear weight * attn weight (0 if invalid)

    const int q   = blockIdx.x;
    const int tid = threadIdx.x;

    // ---- Phase 1: per-point metadata (threads 0..127) ----
    if (tid < 128) {
        const int h  = tid >> 4;       // head
        const int l  = (tid >> 2) & 3; // level
        const int p  = tid & 3;        // point

        // softmax over the 16 points of (q,h): 16-lane shuffle group
        float lg = oa[(size_t)q * 384 + 256 + h * 16 + l * 4 + p];
        float mx = lg;
        #pragma unroll
        for (int m = 8; m; m >>= 1) mx = fmaxf(mx, __shfl_xor_sync(~0u, mx, m));
        float ex = __expf(lg - mx);
        float sm = ex;
        #pragma unroll
        for (int m = 8; m; m >>= 1) sm += __shfl_xor_sync(~0u, sm, m);
        const float wn = ex / sm;

        const float ox = oa[(size_t)q * 384 + h * 32 + l * 8 + p * 2 + 0];
        const float oy = oa[(size_t)q * 384 + h * 32 + l * 8 + p * 2 + 1];
        const float cx = ref[(size_t)q * 16 + l * 4 + 0];
        const float cy = ref[(size_t)q * 16 + l * 4 + 1];
        const float rw = ref[(size_t)q * 16 + l * 4 + 2];
        const float rh = ref[(size_t)q * 16 + l * 4 + 3];
        const int H = c_H[l], W = c_W[l];
        const int start = c_start[l];

        const float x = (cx + ox * 0.125f * rw) * (float)W - 0.5f;
        const float y = (cy + oy * 0.125f * rh) * (float)H - 0.5f;
        const float x0f = floorf(x), y0f = floorf(y);
        const int x0 = (int)x0f, y0 = (int)y0f;
        const float wx1 = x - x0f, wy1 = y - y0f;
        const float wx0 = 1.0f - wx1, wy0 = 1.0f - wy1;

        const bool vx0 = (x0 >= 0) && (x0 < W);
        const bool vx1 = (x0 + 1 >= 0) && (x0 + 1 < W);
        const bool vy0 = (y0 >= 0) && (y0 < H);
        const bool vy1 = (y0 + 1 >= 0) && (y0 + 1 < H);

        const int xc0 = min(max(x0, 0), W - 1);
        const int xc1 = min(max(x0 + 1, 0), W - 1);
        const int yc0 = min(max(y0, 0), H - 1);
        const int yc1 = min(max(y0 + 1, 0), H - 1);

        const int hb = h * 32;
        const int r0 = (start + yc0 * W) * CDIM + hb;
        const int r1 = (start + yc1 * W) * CDIM + hb;
        const int b = tid * 4;
        s_off[b + 0] = r0 + xc0 * CDIM;
        s_off[b + 1] = r0 + xc1 * CDIM;
        s_off[b + 2] = r1 + xc0 * CDIM;
        s_off[b + 3] = r1 + xc1 * CDIM;
        s_w[b + 0] = (vy0 && vx0) ? wn * wy0 * wx0 : 0.0f;
        s_w[b + 1] = (vy0 && vx1) ? wn * wy0 * wx1 : 0.0f;
        s_w[b + 2] = (vy1 && vx0) ? wn * wy1 * wx0 : 0.0f;
        s_w[b + 3] = (vy1 && vx1) ? wn * wy1 * wx1 : 0.0f;
    }
    __syncthreads();

    // ---- Phase 2: gather. warp = head; lane: cg=lane>>3 corner, sc channels ----
    const int h    = tid >> 5;
    const int lane = tid & 31;
    const int cg   = lane >> 3;          // corner 0..3
    const int sc   = (lane & 7) * 4;     // channel quad base 0..28

    float4 acc = make_float4(0.f, 0.f, 0.f, 0.f);
    const int mb = h * 64;               // metadata base (h*16 points * 4)

    #pragma unroll
    for (int pt = 0; pt < 16; pt++) {
        const int   o = s_off[mb + pt * 4 + cg];
        const float w = s_w  [mb + pt * 4 + cg];
        const float4 vv = *reinterpret_cast<const float4*>(&v[(size_t)o + sc]);
        acc.x = fmaf(w, vv.x, acc.x);
        acc.y = fmaf(w, vv.y, acc.y);
        acc.z = fmaf(w, vv.z, acc.z);
        acc.w = fmaf(w, vv.w, acc.w);
    }

    // reduce across the 4 corner groups (lanes xor 8, xor 16)
    #pragma unroll
    for (int m = 8; m <= 16; m <<= 1) {
        acc.x += __shfl_xor_sync(~0u, acc.x, m);
        acc.y += __shfl_xor_sync(~0u, acc.y, m);
        acc.z += __shfl_xor_sync(~0u, acc.z, m);
        acc.w += __shfl_xor_sync(~0u, acc.w, m);
    }
    if (lane < 8)
        *reinterpret_cast<float4*>(&mid[(size_t)q * CDIM + h * 32 + sc]) = acc;
}

// ---------------------------------------------------------------------------
// Launch
// ---------------------------------------------------------------------------
extern "C" void kernel_launch(void* const* d_in, const int* in_sizes, int n_in,
                              void* d_out, int out_size)
{
    const float* query  = (const float*)d_in[0];
    const float* ref    = (const float*)d_in[1];
    const float* value  = (const float*)d_in[2];
    const float* W_off  = (const float*)d_in[3];
    const float* b_off  = (const float*)d_in[4];
    const float* W_attn = (const float*)d_in[5];
    const float* b_attn = (const float*)d_in[6];
    const float* W_val  = (const float*)d_in[7];
    const float* b_val  = (const float*)d_in[8];
    const float* W_out  = (const float*)d_in[9];
    const float* b_out  = (const float*)d_in[10];
    float* out = (float*)d_out;

    float *gv, *goa, *gmid;
    __nv_bfloat16 *wh, *wl;
    cudaGetSymbolAddress((void**)&gv,   g_v);
    cudaGetSymbolAddress((void**)&goa,  g_oa);
    cudaGetSymbolAddress((void**)&gmid, g_mid);
    cudaGetSymbolAddress((void**)&wh,   g_wh);
    cudaGetSymbolAddress((void**)&wl,   g_wl);

    cudaFuncSetAttribute(gemm_kres, cudaFuncAttributeMaxDynamicSharedMemorySize,
                         SM_TOTAL);

    const int MT = (LQ + 127) / 128;   // 174
    dim3 gv256(MT, 4);                 // N=256
    dim3 gq384(MT, 6);                 // N=384 (off | attn)

    // 0. weight prep
    prep_all_w<<<(W_TOTAL + 255) / 256, 256>>>(W_val, W_off, W_attn, W_out, wh, wl);

    // 1. v = value @ W_val + b_val
    gemm_kres<<<gv256, 256, SM_TOTAL>>>(value, wh + W_VAL_OFF, wl + W_VAL_OFF,
                                        b_val, b_val, 1 << 30, gv, LQ, 256);
    // 2. [off | attn] = query @ [W_off | W_attn]
    gemm_kres<<<gq384, 256, SM_TOTAL>>>(query, wh + W_OFF_OFF, wl + W_OFF_OFF,
                                        b_off, b_attn, 256, goa, LQ, 384);
    // 3. sampling (softmax fused, two-phase)
    sample_kernel<<<LQ, 256>>>(gv, goa, ref, gmid);
    // 4. out = mid @ W_out + b_out
    gemm_kres<<<gv256, 256, SM_TOTAL>>>(gmid, wh + W_OUT_OFF, wl + W_OUT_OFF,
                                        b_out, b_out, 1 << 30, out, LQ, 256);
}

// round 8
// speedup vs baseline: 1.6384x; 1.0616x over previous
#include <cuda_runtime.h>
#include <cuda_bf16.h>
#include <cstdint>

// ---------------------------------------------------------------------------
// Problem constants
// ---------------------------------------------------------------------------
#define LQ      22223
#define CDIM    256
#define NHEADS  8
#define NLVL    4
#define NPTS    4
#define KDIM    256

__device__ __constant__ int c_H[NLVL]     = {100, 50, 25, 13};
__device__ __constant__ int c_W[NLVL]     = {167, 84, 42, 21};
__device__ __constant__ int c_start[NLVL] = {0, 16700, 20900, 21950};

// ---------------------------------------------------------------------------
// Scratch (device globals; no allocation allowed)
// ---------------------------------------------------------------------------
__device__ float g_v   [LQ * CDIM];   // value @ W_val + b_val
__device__ float g_oa  [LQ * 384];    // [off(256) | attn logits(128)] per row
__device__ float g_mid [LQ * CDIM];   // sampled output, pre-W_out

// Weight splits, transposed to [N,K], packed: WVAL | WOFF | WATTN | WOUT
#define W_VAL_OFF   0
#define W_OFF_OFF   (256 * 256)
#define W_ATTN_OFF  (2 * 256 * 256)
#define W_OUT_OFF   (2 * 256 * 256 + 128 * 256)
#define W_TOTAL     (3 * 256 * 256 + 128 * 256)
__device__ __nv_bfloat16 g_wh[W_TOTAL];
__device__ __nv_bfloat16 g_wl[W_TOTAL];

// ---------------------------------------------------------------------------
// mma.sync / ldmatrix helpers (plain sm_103)
// ---------------------------------------------------------------------------
__device__ __forceinline__ uint32_t smem_u32(const void* p) {
    uint32_t a;
    asm("{ .reg .u64 t; cvta.to.shared.u64 t, %1; cvt.u32.u64 %0, t; }"
        : "=r"(a) : "l"(p));
    return a;
}
__device__ __forceinline__ void ldsm_x4(uint32_t* r, uint32_t addr) {
    asm volatile("ldmatrix.sync.aligned.m8n8.x4.shared.b16 {%0,%1,%2,%3}, [%4];"
                 : "=r"(r[0]), "=r"(r[1]), "=r"(r[2]), "=r"(r[3]) : "r"(addr));
}
__device__ __forceinline__ void mma_bf16(float* d, const uint32_t* a,
                                         const uint32_t* b) {
    asm volatile(
        "mma.sync.aligned.m16n8k16.row.col.f32.bf16.bf16.f32 "
        "{%0,%1,%2,%3}, {%4,%5,%6,%7}, {%8,%9}, {%0,%1,%2,%3};"
        : "+f"(d[0]), "+f"(d[1]), "+f"(d[2]), "+f"(d[3])
        : "r"(a[0]), "r"(a[1]), "r"(a[2]), "r"(a[3]), "r"(b[0]), "r"(b[1]));
}

// ---------------------------------------------------------------------------
// Fused weight prep
// ---------------------------------------------------------------------------
__global__ void prep_all_w(const float* __restrict__ Wv,
                           const float* __restrict__ Wo,
                           const float* __restrict__ Wa,
                           const float* __restrict__ Wu,
                           __nv_bfloat16* __restrict__ wh,
                           __nv_bfloat16* __restrict__ wl)
{
    int i = blockIdx.x * blockDim.x + threadIdx.x;
    if (i >= W_TOTAL) return;
    const float* W;
    int N, local, base;
    if (i < 65536)        { W = Wv; N = 256; base = W_VAL_OFF;  local = i; }
    else if (i < 131072)  { W = Wo; N = 256; base = W_OFF_OFF;  local = i - 65536; }
    else if (i < 163840)  { W = Wa; N = 128; base = W_ATTN_OFF; local = i - 131072; }
    else                  { W = Wu; N = 256; base = W_OUT_OFF;  local = i - 163840; }
    int k = local / N;
    int n = local - k * N;
    float a = W[(size_t)k * N + n];
    __nv_bfloat16 hi = __float2bfloat16(a);
    __nv_bfloat16 lo = __float2bfloat16(a - __bfloat162float(hi));
    wh[(size_t)base + (size_t)n * KDIM + k] = hi;
    wl[(size_t)base + (size_t)n * KDIM + k] = lo;
}

// ---------------------------------------------------------------------------
// K-resident split-bf16 mma.sync GEMM core (256 thr, 8 warps, warp tile 32x32)
// Shared by the merged front GEMM and the output GEMM.
// ---------------------------------------------------------------------------
#define LDK 264
#define SM_AH 0
#define SM_AL (128 * LDK * 2)
#define SM_BH (2 * 128 * LDK * 2)
#define SM_BL (SM_BH + 64 * LDK * 2)
#define SM_TOTAL (SM_BL + 64 * LDK * 2)   // 202752

__device__ __forceinline__ void gemm_core(
    const float* __restrict__ A,
    const __nv_bfloat16* __restrict__ bh,   // B hi base for this col-tile [64,K]
    const __nv_bfloat16* __restrict__ bl,
    const float* __restrict__ bias0,
    const float* __restrict__ bias1,
    int nsplit, int col0,
    float* __restrict__ C, int M, int N, int m0, char* smem)
{
    __nv_bfloat16* Ah = reinterpret_cast<__nv_bfloat16*>(smem + SM_AH);
    __nv_bfloat16* Al = reinterpret_cast<__nv_bfloat16*>(smem + SM_AL);
    __nv_bfloat16* Bh = reinterpret_cast<__nv_bfloat16*>(smem + SM_BH);
    __nv_bfloat16* Bl = reinterpret_cast<__nv_bfloat16*>(smem + SM_BL);

    const int tid  = threadIdx.x;
    const int wid  = tid >> 5;
    const int lane = tid & 31;
    const int warp_m = wid & 3;
    const int warp_n = wid >> 2;

    // ---- load A (fp32) and split to hi/lo bf16 in SMEM ----
    {
        const int r  = tid >> 1;
        const int cb = (tid & 1) * 128;
        const int gr = m0 + r;
        #pragma unroll
        for (int j = 0; j < 32; j++) {
            const int c4 = cb + j * 4;
            float4 v = make_float4(0.f, 0.f, 0.f, 0.f);
            if (gr < M)
                v = *reinterpret_cast<const float4*>(&A[(size_t)gr * KDIM + c4]);
            __nv_bfloat162 h01 = __floats2bfloat162_rn(v.x, v.y);
            __nv_bfloat162 h23 = __floats2bfloat162_rn(v.z, v.w);
            __nv_bfloat162 l01 = __floats2bfloat162_rn(
                v.x - __bfloat162float(h01.x), v.y - __bfloat162float(h01.y));
            __nv_bfloat162 l23 = __floats2bfloat162_rn(
                v.z - __bfloat162float(h23.x), v.w - __bfloat162float(h23.y));
            const int o = r * LDK + c4;
            *reinterpret_cast<__nv_bfloat162*>(&Ah[o])     = h01;
            *reinterpret_cast<__nv_bfloat162*>(&Ah[o + 2]) = h23;
            *reinterpret_cast<__nv_bfloat162*>(&Al[o])     = l01;
            *reinterpret_cast<__nv_bfloat162*>(&Al[o + 2]) = l23;
        }
    }
    // ---- load B hi/lo ([64,K] slice starting at bh/bl) ----
    #pragma unroll
    for (int i = 0; i < 8; i++) {
        const int idx = tid + (i << 8);
        const int r  = idx >> 5;
        const int c8 = (idx & 31) << 3;
        const size_t g = (size_t)r * KDIM + c8;
        const int o = r * LDK + c8;
        *reinterpret_cast<uint4*>(&Bh[o]) = *reinterpret_cast<const uint4*>(&bh[g]);
        *reinterpret_cast<uint4*>(&Bl[o]) = *reinterpret_cast<const uint4*>(&bl[g]);
    }
    __syncthreads();

    float acc[2][4][4];
    #pragma unroll
    for (int i = 0; i < 2; i++)
        #pragma unroll
        for (int j = 0; j < 4; j++)
            #pragma unroll
            for (int k = 0; k < 4; k++) acc[i][j][k] = 0.0f;

    const uint32_t sAh = smem_u32(Ah), sAl = smem_u32(Al);
    const uint32_t sBh = smem_u32(Bh), sBl = smem_u32(Bl);
    const int a_row  = warp_m * 32 + (lane & 15);
    const int a_colb = (lane >> 4) << 3;
    const int b_row  = warp_n * 32 + (lane & 7) + ((lane >> 4) << 3);
    const int b_colb = ((lane >> 3) & 1) << 3;

    #pragma unroll
    for (int ks = 0; ks < 16; ks++) {
        const int kc = ks << 4;
        uint32_t fah[2][4], fal[2][4], fbh[2][4], fbl[2][4];
        #pragma unroll
        for (int mt = 0; mt < 2; mt++) {
            const uint32_t off = (uint32_t)(((a_row + mt * 16) * LDK + kc + a_colb) * 2);
            ldsm_x4(fah[mt], sAh + off);
            ldsm_x4(fal[mt], sAl + off);
        }
        #pragma unroll
        for (int np = 0; np < 2; np++) {
            const uint32_t off = (uint32_t)(((b_row + np * 16) * LDK + kc + b_colb) * 2);
            ldsm_x4(fbh[np], sBh + off);
            ldsm_x4(fbl[np], sBl + off);
        }
        #pragma unroll
        for (int mt = 0; mt < 2; mt++)
            #pragma unroll
            for (int nt = 0; nt < 4; nt++)
                mma_bf16(acc[mt][nt], fah[mt], &fbh[nt >> 1][(nt & 1) * 2]);
        #pragma unroll
        for (int mt = 0; mt < 2; mt++)
            #pragma unroll
            for (int nt = 0; nt < 4; nt++)
                mma_bf16(acc[mt][nt], fah[mt], &fbl[nt >> 1][(nt & 1) * 2]);
        #pragma unroll
        for (int mt = 0; mt < 2; mt++)
            #pragma unroll
            for (int nt = 0; nt < 4; nt++)
                mma_bf16(acc[mt][nt], fal[mt], &fbh[nt >> 1][(nt & 1) * 2]);
    }

    const int er = lane >> 2;
    const int ec = (lane & 3) << 1;
    #pragma unroll
    for (int mt = 0; mt < 2; mt++) {
        #pragma unroll
        for (int nt = 0; nt < 4; nt++) {
            const int col = col0 + warp_n * 32 + nt * 8 + ec;
            const float b0 = (col < nsplit)     ? bias0[col]     : bias1[col - nsplit];
            const float b1 = (col + 1 < nsplit) ? bias0[col + 1] : bias1[col + 1 - nsplit];
            const int r0 = m0 + warp_m * 32 + mt * 16 + er;
            if (r0 < M) {
                float2 o = make_float2(acc[mt][nt][0] + b0, acc[mt][nt][1] + b1);
                *reinterpret_cast<float2*>(&C[(size_t)r0 * N + col]) = o;
            }
            if (r0 + 8 < M) {
                float2 o = make_float2(acc[mt][nt][2] + b0, acc[mt][nt][3] + b1);
                *reinterpret_cast<float2*>(&C[(size_t)(r0 + 8) * N + col]) = o;
            }
        }
    }
}

// Merged front GEMM: grid.y 0..3 -> value GEMM (N=256, C=g_v),
//                    grid.y 4..9 -> query GEMM (N=384, C=g_oa, bias split 256)
__global__ __launch_bounds__(256)
void gemm_front(const float* __restrict__ value,
                const float* __restrict__ query,
                const __nv_bfloat16* __restrict__ wh,
                const __nv_bfloat16* __restrict__ wl,
                const float* __restrict__ b_val,
                const float* __restrict__ b_off,
                const float* __restrict__ b_attn,
                float* __restrict__ Cv, float* __restrict__ Coa)
{
    extern __shared__ __align__(16) char smem[];
    const int y = blockIdx.y;
    const int m0 = blockIdx.x * 128;
    if (y < 4) {
        const int col0 = y * 64;
        gemm_core(value, wh + W_VAL_OFF + (size_t)col0 * KDIM,
                  wl + W_VAL_OFF + (size_t)col0 * KDIM,
                  b_val, b_val, 1 << 30, col0, Cv, LQ, 256, m0, smem);
    } else {
        const int col0 = (y - 4) * 64;
        gemm_core(query, wh + W_OFF_OFF + (size_t)col0 * KDIM,
                  wl + W_OFF_OFF + (size_t)col0 * KDIM,
                  b_off, b_attn, 256, col0, Coa, LQ, 384, m0, smem);
    }
}

// Output GEMM
__global__ __launch_bounds__(256)
void gemm_out(const float* __restrict__ mid,
              const __nv_bfloat16* __restrict__ wh,
              const __nv_bfloat16* __restrict__ wl,
              const float* __restrict__ b_out,
              float* __restrict__ C)
{
    extern __shared__ __align__(16) char smem[];
    const int col0 = blockIdx.y * 64;
    gemm_core(mid, wh + W_OUT_OFF + (size_t)col0 * KDIM,
              wl + W_OUT_OFF + (size_t)col0 * KDIM,
              b_out, b_out, 1 << 30, col0, C, LQ, 256, blockIdx.x * 128, smem);
}

// ---------------------------------------------------------------------------
// Sampling: phase 1 per-point metadata (int2-fused), phase 2 gather.
// ---------------------------------------------------------------------------
__global__ __launch_bounds__(256) void sample_kernel(
    const float* __restrict__ v, const float* __restrict__ oa,
    const float* __restrict__ ref, float* __restrict__ mid)
{
    __shared__ int2 s_meta[128 * 4];   // {elem offset (h*32 folded), weight bits}

    const int q   = blockIdx.x;
    const int tid = threadIdx.x;

    // ---- Phase 1 ----
    if (tid < 128) {
        const int h  = tid >> 4;
        const int l  = (tid >> 2) & 3;
        const int p  = tid & 3;

        float lg = oa[(size_t)q * 384 + 256 + h * 16 + l * 4 + p];
        float mx = lg;
        #pragma unroll
        for (int m = 8; m; m >>= 1) mx = fmaxf(mx, __shfl_xor_sync(~0u, mx, m));
        float ex = __expf(lg - mx);
        float sm = ex;
        #pragma unroll
        for (int m = 8; m; m >>= 1) sm += __shfl_xor_sync(~0u, sm, m);
        const float wn = ex / sm;

        const float ox = oa[(size_t)q * 384 + h * 32 + l * 8 + p * 2 + 0];
        const float oy = oa[(size_t)q * 384 + h * 32 + l * 8 + p * 2 + 1];
        const float cx = ref[(size_t)q * 16 + l * 4 + 0];
        const float cy = ref[(size_t)q * 16 + l * 4 + 1];
        const float rw = ref[(size_t)q * 16 + l * 4 + 2];
        const float rh = ref[(size_t)q * 16 + l * 4 + 3];
        const int H = c_H[l], W = c_W[l];
        const int start = c_start[l];

        const float x = (cx + ox * 0.125f * rw) * (float)W - 0.5f;
        const float y = (cy + oy * 0.125f * rh) * (float)H - 0.5f;
        const float x0f = floorf(x), y0f = floorf(y);
        const int x0 = (int)x0f, y0 = (int)y0f;
        const float wx1 = x - x0f, wy1 = y - y0f;
        const float wx0 = 1.0f - wx1, wy0 = 1.0f - wy1;

        const bool vx0 = (x0 >= 0) && (x0 < W);
        const bool vx1 = (x0 + 1 >= 0) && (x0 + 1 < W);
        const bool vy0 = (y0 >= 0) && (y0 < H);
        const bool vy1 = (y0 + 1 >= 0) && (y0 + 1 < H);

        const int xc0 = min(max(x0, 0), W - 1);
        const int xc1 = min(max(x0 + 1, 0), W - 1);
        const int yc0 = min(max(y0, 0), H - 1);
        const int yc1 = min(max(y0 + 1, 0), H - 1);

        const int hb = h * 32;
        const int r0 = (start + yc0 * W) * CDIM + hb;
        const int r1 = (start + yc1 * W) * CDIM + hb;
        const int b = tid * 4;
        s_meta[b + 0] = make_int2(r0 + xc0 * CDIM,
            __float_as_int((vy0 && vx0) ? wn * wy0 * wx0 : 0.0f));
        s_meta[b + 1] = make_int2(r0 + xc1 * CDIM,
            __float_as_int((vy0 && vx1) ? wn * wy0 * wx1 : 0.0f));
        s_meta[b + 2] = make_int2(r1 + xc0 * CDIM,
            __float_as_int((vy1 && vx0) ? wn * wy1 * wx0 : 0.0f));
        s_meta[b + 3] = make_int2(r1 + xc1 * CDIM,
            __float_as_int((vy1 && vx1) ? wn * wy1 * wx1 : 0.0f));
    }
    __syncthreads();

    // ---- Phase 2: gather ----
    const int h    = tid >> 5;
    const int lane = tid & 31;
    const int cg   = lane >> 3;
    const int sc   = (lane & 7) * 4;
    const float* vp = v + sc;          // hoisted channel offset

    float4 acc = make_float4(0.f, 0.f, 0.f, 0.f);
    const int2* mp = &s_meta[h * 64 + cg];

    #pragma unroll
    for (int pt = 0; pt < 16; pt++) {
        const int2  m = mp[pt * 4];
        const float w = __int_as_float(m.y);
        const float4 vv = *reinterpret_cast<const float4*>(vp + m.x);
        acc.x = fmaf(w, vv.x, acc.x);
        acc.y = fmaf(w, vv.y, acc.y);
        acc.z = fmaf(w, vv.z, acc.z);
        acc.w = fmaf(w, vv.w, acc.w);
    }

    #pragma unroll
    for (int m = 8; m <= 16; m <<= 1) {
        acc.x += __shfl_xor_sync(~0u, acc.x, m);
        acc.y += __shfl_xor_sync(~0u, acc.y, m);
        acc.z += __shfl_xor_sync(~0u, acc.z, m);
        acc.w += __shfl_xor_sync(~0u, acc.w, m);
    }
    if (lane < 8)
        *reinterpret_cast<float4*>(&mid[(size_t)q * CDIM + h * 32 + sc]) = acc;
}

// ---------------------------------------------------------------------------
// Launch
// ---------------------------------------------------------------------------
extern "C" void kernel_launch(void* const* d_in, const int* in_sizes, int n_in,
                              void* d_out, int out_size)
{
    const float* query  = (const float*)d_in[0];
    const float* ref    = (const float*)d_in[1];
    const float* value  = (const float*)d_in[2];
    const float* W_off  = (const float*)d_in[3];
    const float* b_off  = (const float*)d_in[4];
    const float* W_attn = (const float*)d_in[5];
    const float* b_attn = (const float*)d_in[6];
    const float* W_val  = (const float*)d_in[7];
    const float* b_val  = (const float*)d_in[8];
    const float* W_out  = (const float*)d_in[9];
    const float* b_out  = (const float*)d_in[10];
    float* out = (float*)d_out;

    float *gv, *goa, *gmid;
    __nv_bfloat16 *wh, *wl;
    cudaGetSymbolAddress((void**)&gv,   g_v);
    cudaGetSymbolAddress((void**)&goa,  g_oa);
    cudaGetSymbolAddress((void**)&gmid, g_mid);
    cudaGetSymbolAddress((void**)&wh,   g_wh);
    cudaGetSymbolAddress((void**)&wl,   g_wl);

    cudaFuncSetAttribute(gemm_front, cudaFuncAttributeMaxDynamicSharedMemorySize,
                         SM_TOTAL);
    cudaFuncSetAttribute(gemm_out, cudaFuncAttributeMaxDynamicSharedMemorySize,
                         SM_TOTAL);

    const int MT = (LQ + 127) / 128;   // 174

    // 0. weight prep
    prep_all_w<<<(W_TOTAL + 255) / 256, 256>>>(W_val, W_off, W_attn, W_out, wh, wl);

    // 1. merged front GEMMs: v = value@W_val ; [off|attn] = query@[W_off|W_attn]
    gemm_front<<<dim3(MT, 10), 256, SM_TOTAL>>>(value, query, wh, wl,
                                                b_val, b_off, b_attn, gv, goa);
    // 2. sampling (softmax fused, two-phase)
    sample_kernel<<<LQ, 256>>>(gv, goa, ref, gmid);
    // 3. out = mid @ W_out + b_out
    gemm_out<<<dim3(MT, 4), 256, SM_TOTAL>>>(gmid, wh, wl, b_out, out);
}

// round 9
// speedup vs baseline: 1.6529x; 1.0089x over previous
#include <cuda_runtime.h>
#include <cuda_bf16.h>
#include <cstdint>

// ---------------------------------------------------------------------------
// Problem constants
// ---------------------------------------------------------------------------
#define LQ      22223
#define CDIM    256
#define NHEADS  8
#define NLVL    4
#define NPTS    4
#define KDIM    256

__device__ __constant__ int c_H[NLVL]     = {100, 50, 25, 13};
__device__ __constant__ int c_W[NLVL]     = {167, 84, 42, 21};
__device__ __constant__ int c_start[NLVL] = {0, 16700, 20900, 21950};

// ---------------------------------------------------------------------------
// Scratch (device globals; no allocation allowed)
// ---------------------------------------------------------------------------
__device__ float g_v   [LQ * CDIM];   // value @ W_val + b_val
__device__ float g_oa  [LQ * 384];    // [off(256) | attn logits(128)] per row
__device__ float g_mid [LQ * CDIM];   // sampled output, pre-W_out

// Weight splits, transposed to [N,K], packed: WVAL | WOFF | WATTN | WOUT
#define W_VAL_OFF   0
#define W_OFF_OFF   (256 * 256)
#define W_ATTN_OFF  (2 * 256 * 256)
#define W_OUT_OFF   (2 * 256 * 256 + 128 * 256)
#define W_TOTAL     (3 * 256 * 256 + 128 * 256)
__device__ __nv_bfloat16 g_wh[W_TOTAL];
__device__ __nv_bfloat16 g_wl[W_TOTAL];

// ---------------------------------------------------------------------------
// mma.sync / ldmatrix helpers (plain sm_103)
// ---------------------------------------------------------------------------
__device__ __forceinline__ uint32_t smem_u32(const void* p) {
    uint32_t a;
    asm("{ .reg .u64 t; cvta.to.shared.u64 t, %1; cvt.u32.u64 %0, t; }"
        : "=r"(a) : "l"(p));
    return a;
}
__device__ __forceinline__ void ldsm_x4(uint32_t* r, uint32_t addr) {
    asm volatile("ldmatrix.sync.aligned.m8n8.x4.shared.b16 {%0,%1,%2,%3}, [%4];"
                 : "=r"(r[0]), "=r"(r[1]), "=r"(r[2]), "=r"(r[3]) : "r"(addr));
}
__device__ __forceinline__ void mma_bf16(float* d, const uint32_t* a,
                                         const uint32_t* b) {
    asm volatile(
        "mma.sync.aligned.m16n8k16.row.col.f32.bf16.bf16.f32 "
        "{%0,%1,%2,%3}, {%4,%5,%6,%7}, {%8,%9}, {%0,%1,%2,%3};"
        : "+f"(d[0]), "+f"(d[1]), "+f"(d[2]), "+f"(d[3])
        : "r"(a[0]), "r"(a[1]), "r"(a[2]), "r"(a[3]), "r"(b[0]), "r"(b[1]));
}

// ---------------------------------------------------------------------------
// Fused weight prep
// ---------------------------------------------------------------------------
__global__ void prep_all_w(const float* __restrict__ Wv,
                           const float* __restrict__ Wo,
                           const float* __restrict__ Wa,
                           const float* __restrict__ Wu,
                           __nv_bfloat16* __restrict__ wh,
                           __nv_bfloat16* __restrict__ wl)
{
    int i = blockIdx.x * blockDim.x + threadIdx.x;
    if (i >= W_TOTAL) return;
    const float* W;
    int N, local, base;
    if (i < 65536)        { W = Wv; N = 256; base = W_VAL_OFF;  local = i; }
    else if (i < 131072)  { W = Wo; N = 256; base = W_OFF_OFF;  local = i - 65536; }
    else if (i < 163840)  { W = Wa; N = 128; base = W_ATTN_OFF; local = i - 131072; }
    else                  { W = Wu; N = 256; base = W_OUT_OFF;  local = i - 163840; }
    int k = local / N;
    int n = local - k * N;
    float a = W[(size_t)k * N + n];
    __nv_bfloat16 hi = __float2bfloat16(a);
    __nv_bfloat16 lo = __float2bfloat16(a - __bfloat162float(hi));
    wh[(size_t)base + (size_t)n * KDIM + k] = hi;
    wl[(size_t)base + (size_t)n * KDIM + k] = lo;
}

// ---------------------------------------------------------------------------
// K-resident split-bf16 mma.sync GEMM core (256 thr, 8 warps, warp tile 32x32)
// Fragment double-buffering across K-steps for latency hiding.
// ---------------------------------------------------------------------------
#define LDK 264
#define SM_AH 0
#define SM_AL (128 * LDK * 2)
#define SM_BH (2 * 128 * LDK * 2)
#define SM_BL (SM_BH + 64 * LDK * 2)
#define SM_TOTAL (SM_BL + 64 * LDK * 2)   // 202752

__device__ __forceinline__ void gemm_core(
    const float* __restrict__ A,
    const __nv_bfloat16* __restrict__ bh,   // B hi base for this col-tile [64,K]
    const __nv_bfloat16* __restrict__ bl,
    const float* __restrict__ bias0,
    const float* __restrict__ bias1,
    int nsplit, int col0,
    float* __restrict__ C, int M, int N, int m0, char* smem)
{
    __nv_bfloat16* Ah = reinterpret_cast<__nv_bfloat16*>(smem + SM_AH);
    __nv_bfloat16* Al = reinterpret_cast<__nv_bfloat16*>(smem + SM_AL);
    __nv_bfloat16* Bh = reinterpret_cast<__nv_bfloat16*>(smem + SM_BH);
    __nv_bfloat16* Bl = reinterpret_cast<__nv_bfloat16*>(smem + SM_BL);

    const int tid  = threadIdx.x;
    const int wid  = tid >> 5;
    const int lane = tid & 31;
    const int warp_m = wid & 3;
    const int warp_n = wid >> 2;

    // ---- load A (fp32) and split to hi/lo bf16 in SMEM ----
    {
        const int r  = tid >> 1;
        const int cb = (tid & 1) * 128;
        const int gr = m0 + r;
        #pragma unroll
        for (int j = 0; j < 32; j++) {
            const int c4 = cb + j * 4;
            float4 v = make_float4(0.f, 0.f, 0.f, 0.f);
            if (gr < M)
                v = *reinterpret_cast<const float4*>(&A[(size_t)gr * KDIM + c4]);
            __nv_bfloat162 h01 = __floats2bfloat162_rn(v.x, v.y);
            __nv_bfloat162 h23 = __floats2bfloat162_rn(v.z, v.w);
            __nv_bfloat162 l01 = __floats2bfloat162_rn(
                v.x - __bfloat162float(h01.x), v.y - __bfloat162float(h01.y));
            __nv_bfloat162 l23 = __floats2bfloat162_rn(
                v.z - __bfloat162float(h23.x), v.w - __bfloat162float(h23.y));
            const int o = r * LDK + c4;
            *reinterpret_cast<__nv_bfloat162*>(&Ah[o])     = h01;
            *reinterpret_cast<__nv_bfloat162*>(&Ah[o + 2]) = h23;
            *reinterpret_cast<__nv_bfloat162*>(&Al[o])     = l01;
            *reinterpret_cast<__nv_bfloat162*>(&Al[o + 2]) = l23;
        }
    }
    // ---- load B hi/lo ([64,K] slice starting at bh/bl) ----
    #pragma unroll
    for (int i = 0; i < 8; i++) {
        const int idx = tid + (i << 8);
        const int r  = idx >> 5;
        const int c8 = (idx & 31) << 3;
        const size_t g = (size_t)r * KDIM + c8;
        const int o = r * LDK + c8;
        *reinterpret_cast<uint4*>(&Bh[o]) = *reinterpret_cast<const uint4*>(&bh[g]);
        *reinterpret_cast<uint4*>(&Bl[o]) = *reinterpret_cast<const uint4*>(&bl[g]);
    }
    __syncthreads();

    float acc[2][4][4];
    #pragma unroll
    for (int i = 0; i < 2; i++)
        #pragma unroll
        for (int j = 0; j < 4; j++)
            #pragma unroll
            for (int k = 0; k < 4; k++) acc[i][j][k] = 0.0f;

    const uint32_t sAh = smem_u32(Ah), sAl = smem_u32(Al);
    const uint32_t sBh = smem_u32(Bh), sBl = smem_u32(Bl);
    const int a_row  = warp_m * 32 + (lane & 15);
    const int a_colb = (lane >> 4) << 3;
    const int b_row  = warp_n * 32 + (lane & 7) + ((lane >> 4) << 3);
    const int b_colb = ((lane >> 3) & 1) << 3;

    // Fragment double buffers: [buf][tile][4]
    uint32_t fah[2][2][4], fal[2][2][4], fbh[2][2][4], fbl[2][2][4];

    #define LOAD_FRAGS(buf, kc)                                                  \
        do {                                                                     \
            _Pragma("unroll")                                                    \
            for (int mt = 0; mt < 2; mt++) {                                     \
                const uint32_t off =                                             \
                    (uint32_t)(((a_row + mt * 16) * LDK + (kc) + a_colb) * 2);   \
                ldsm_x4(fah[buf][mt], sAh + off);                                \
                ldsm_x4(fal[buf][mt], sAl + off);                                \
            }                                                                    \
            _Pragma("unroll")                                                    \
            for (int np = 0; np < 2; np++) {                                     \
                const uint32_t off =                                             \
                    (uint32_t)(((b_row + np * 16) * LDK + (kc) + b_colb) * 2);   \
                ldsm_x4(fbh[buf][np], sBh + off);                                \
                ldsm_x4(fbl[buf][np], sBl + off);                                \
            }                                                                    \
        } while (0)

    LOAD_FRAGS(0, 0);

    #pragma unroll
    for (int ks = 0; ks < 16; ks++) {
        const int cur = ks & 1;
        const int nxt = cur ^ 1;
        if (ks < 15) LOAD_FRAGS(nxt, (ks + 1) << 4);

        #pragma unroll
        for (int mt = 0; mt < 2; mt++)
            #pragma unroll
            for (int nt = 0; nt < 4; nt++)
                mma_bf16(acc[mt][nt], fah[cur][mt], &fbh[cur][nt >> 1][(nt & 1) * 2]);
        #pragma unroll
        for (int mt = 0; mt < 2; mt++)
            #pragma unroll
            for (int nt = 0; nt < 4; nt++)
                mma_bf16(acc[mt][nt], fah[cur][mt], &fbl[cur][nt >> 1][(nt & 1) * 2]);
        #pragma unroll
        for (int mt = 0; mt < 2; mt++)
            #pragma unroll
            for (int nt = 0; nt < 4; nt++)
                mma_bf16(acc[mt][nt], fal[cur][mt], &fbh[cur][nt >> 1][(nt & 1) * 2]);
    }
    #undef LOAD_FRAGS

    const int er = lane >> 2;
    const int ec = (lane & 3) << 1;
    #pragma unroll
    for (int mt = 0; mt < 2; mt++) {
        #pragma unroll
        for (int nt = 0; nt < 4; nt++) {
            const int col = col0 + warp_n * 32 + nt * 8 + ec;
            const float b0 = (col < nsplit)     ? bias0[col]     : bias1[col - nsplit];
            const float b1 = (col + 1 < nsplit) ? bias0[col + 1] : bias1[col + 1 - nsplit];
            const int r0 = m0 + warp_m * 32 + mt * 16 + er;
            if (r0 < M) {
                float2 o = make_float2(acc[mt][nt][0] + b0, acc[mt][nt][1] + b1);
                *reinterpret_cast<float2*>(&C[(size_t)r0 * N + col]) = o;
            }
            if (r0 + 8 < M) {
                float2 o = make_float2(acc[mt][nt][2] + b0, acc[mt][nt][3] + b1);
                *reinterpret_cast<float2*>(&C[(size_t)(r0 + 8) * N + col]) = o;
            }
        }
    }
}

// Merged front GEMM: grid.y 0..3 -> value GEMM (N=256, C=g_v),
//                    grid.y 4..9 -> query GEMM (N=384, C=g_oa, bias split 256)
__global__ __launch_bounds__(256)
void gemm_front(const float* __restrict__ value,
                const float* __restrict__ query,
                const __nv_bfloat16* __restrict__ wh,
                const __nv_bfloat16* __restrict__ wl,
                const float* __restrict__ b_val,
                const float* __restrict__ b_off,
                const float* __restrict__ b_attn,
                float* __restrict__ Cv, float* __restrict__ Coa)
{
    extern __shared__ __align__(16) char smem[];
    const int y = blockIdx.y;
    const int m0 = blockIdx.x * 128;
    if (y < 4) {
        const int col0 = y * 64;
        gemm_core(value, wh + W_VAL_OFF + (size_t)col0 * KDIM,
                  wl + W_VAL_OFF + (size_t)col0 * KDIM,
                  b_val, b_val, 1 << 30, col0, Cv, LQ, 256, m0, smem);
    } else {
        const int col0 = (y - 4) * 64;
        gemm_core(query, wh + W_OFF_OFF + (size_t)col0 * KDIM,
                  wl + W_OFF_OFF + (size_t)col0 * KDIM,
                  b_off, b_attn, 256, col0, Coa, LQ, 384, m0, smem);
    }
}

// Output GEMM
__global__ __launch_bounds__(256)
void gemm_out(const float* __restrict__ mid,
              const __nv_bfloat16* __restrict__ wh,
              const __nv_bfloat16* __restrict__ wl,
              const float* __restrict__ b_out,
              float* __restrict__ C)
{
    extern __shared__ __align__(16) char smem[];
    const int col0 = blockIdx.y * 64;
    gemm_core(mid, wh + W_OUT_OFF + (size_t)col0 * KDIM,
              wl + W_OUT_OFF + (size_t)col0 * KDIM,
              b_out, b_out, 1 << 30, col0, C, LQ, 256, blockIdx.x * 128, smem);
}

// ---------------------------------------------------------------------------
// Sampling: phase 1 per-point metadata (int2-fused), phase 2 gather.
// ---------------------------------------------------------------------------
__global__ __launch_bounds__(256) void sample_kernel(
    const float* __restrict__ v, const float* __restrict__ oa,
    const float* __restrict__ ref, float* __restrict__ mid)
{
    __shared__ int2 s_meta[128 * 4];   // {elem offset (h*32 folded), weight bits}

    const int q   = blockIdx.x;
    const int tid = threadIdx.x;

    // ---- Phase 1 ----
    if (tid < 128) {
        const int h  = tid >> 4;
        const int l  = (tid >> 2) & 3;
        const int p  = tid & 3;

        float lg = oa[(size_t)q * 384 + 256 + h * 16 + l * 4 + p];
        float mx = lg;
        #pragma unroll
        for (int m = 8; m; m >>= 1) mx = fmaxf(mx, __shfl_xor_sync(~0u, mx, m));
        float ex = __expf(lg - mx);
        float sm = ex;
        #pragma unroll
        for (int m = 8; m; m >>= 1) sm += __shfl_xor_sync(~0u, sm, m);
        const float wn = ex / sm;

        const float ox = oa[(size_t)q * 384 + h * 32 + l * 8 + p * 2 + 0];
        const float oy = oa[(size_t)q * 384 + h * 32 + l * 8 + p * 2 + 1];
        const float cx = ref[(size_t)q * 16 + l * 4 + 0];
        const float cy = ref[(size_t)q * 16 + l * 4 + 1];
        const float rw = ref[(size_t)q * 16 + l * 4 + 2];
        const float rh = ref[(size_t)q * 16 + l * 4 + 3];
        const int H = c_H[l], W = c_W[l];
        const int start = c_start[l];

        const float x = (cx + ox * 0.125f * rw) * (float)W - 0.5f;
        const float y = (cy + oy * 0.125f * rh) * (float)H - 0.5f;
        const float x0f = floorf(x), y0f = floorf(y);
        const int x0 = (int)x0f, y0 = (int)y0f;
        const float wx1 = x - x0f, wy1 = y - y0f;
        const float wx0 = 1.0f - wx1, wy0 = 1.0f - wy1;

        const bool vx0 = (x0 >= 0) && (x0 < W);
        const bool vx1 = (x0 + 1 >= 0) && (x0 + 1 < W);
        const bool vy0 = (y0 >= 0) && (y0 < H);
        const bool vy1 = (y0 + 1 >= 0) && (y0 + 1 < H);

        const int xc0 = min(max(x0, 0), W - 1);
        const int xc1 = min(max(x0 + 1, 0), W - 1);
        const int yc0 = min(max(y0, 0), H - 1);
        const int yc1 = min(max(y0 + 1, 0), H - 1);

        const int hb = h * 32;
        const int r0 = (start + yc0 * W) * CDIM + hb;
        const int r1 = (start + yc1 * W) * CDIM + hb;
        const int b = tid * 4;
        s_meta[b + 0] = make_int2(r0 + xc0 * CDIM,
            __float_as_int((vy0 && vx0) ? wn * wy0 * wx0 : 0.0f));
        s_meta[b + 1] = make_int2(r0 + xc1 * CDIM,
            __float_as_int((vy0 && vx1) ? wn * wy0 * wx1 : 0.0f));
        s_meta[b + 2] = make_int2(r1 + xc0 * CDIM,
            __float_as_int((vy1 && vx0) ? wn * wy1 * wx0 : 0.0f));
        s_meta[b + 3] = make_int2(r1 + xc1 * CDIM,
            __float_as_int((vy1 && vx1) ? wn * wy1 * wx1 : 0.0f));
    }
    __syncthreads();

    // ---- Phase 2: gather ----
    const int h    = tid >> 5;
    const int lane = tid & 31;
    const int cg   = lane >> 3;
    const int sc   = (lane & 7) * 4;
    const float* vp = v + sc;          // hoisted channel offset

    float4 acc = make_float4(0.f, 0.f, 0.f, 0.f);
    const int2* mp = &s_meta[h * 64 + cg];

    #pragma unroll
    for (int pt = 0; pt < 16; pt++) {
        const int2  m = mp[pt * 4];
        const float w = __int_as_float(m.y);
        const float4 vv = *reinterpret_cast<const float4*>(vp + m.x);
        acc.x = fmaf(w, vv.x, acc.x);
        acc.y = fmaf(w, vv.y, acc.y);
        acc.z = fmaf(w, vv.z, acc.z);
        acc.w = fmaf(w, vv.w, acc.w);
    }

    #pragma unroll
    for (int m = 8; m <= 16; m <<= 1) {
        acc.x += __shfl_xor_sync(~0u, acc.x, m);
        acc.y += __shfl_xor_sync(~0u, acc.y, m);
        acc.z += __shfl_xor_sync(~0u, acc.z, m);
        acc.w += __shfl_xor_sync(~0u, acc.w, m);
    }
    if (lane < 8)
        *reinterpret_cast<float4*>(&mid[(size_t)q * CDIM + h * 32 + sc]) = acc;
}

// ---------------------------------------------------------------------------
// Launch
// ---------------------------------------------------------------------------
extern "C" void kernel_launch(void* const* d_in, const int* in_sizes, int n_in,
                              void* d_out, int out_size)
{
    const float* query  = (const float*)d_in[0];
    const float* ref    = (const float*)d_in[1];
    const float* value  = (const float*)d_in[2];
    const float* W_off  = (const float*)d_in[3];
    const float* b_off  = (const float*)d_in[4];
    const float* W_attn = (const float*)d_in[5];
    const float* b_attn = (const float*)d_in[6];
    const float* W_val  = (const float*)d_in[7];
    const float* b_val  = (const float*)d_in[8];
    const float* W_out  = (const float*)d_in[9];
    const float* b_out  = (const float*)d_in[10];
    float* out = (float*)d_out;

    float *gv, *goa, *gmid;
    __nv_bfloat16 *wh, *wl;
    cudaGetSymbolAddress((void**)&gv,   g_v);
    cudaGetSymbolAddress((void**)&goa,  g_oa);
    cudaGetSymbolAddress((void**)&gmid, g_mid);
    cudaGetSymbolAddress((void**)&wh,   g_wh);
    cudaGetSymbolAddress((void**)&wl,   g_wl);

    cudaFuncSetAttribute(gemm_front, cudaFuncAttributeMaxDynamicSharedMemorySize,
                         SM_TOTAL);
    cudaFuncSetAttribute(gemm_out, cudaFuncAttributeMaxDynamicSharedMemorySize,
                         SM_TOTAL);

    const int MT = (LQ + 127) / 128;   // 174

    // 0. weight prep
    prep_all_w<<<(W_TOTAL + 255) / 256, 256>>>(W_val, W_off, W_attn, W_out, wh, wl);

    // 1. merged front GEMMs
    gemm_front<<<dim3(MT, 10), 256, SM_TOTAL>>>(value, query, wh, wl,
                                                b_val, b_off, b_attn, gv, goa);
    // 2. sampling (softmax fused, two-phase)
    sample_kernel<<<LQ, 256>>>(gv, goa, ref, gmid);
    // 3. out = mid @ W_out + b_out
    gemm_out<<<dim3(MT, 4), 256, SM_TOTAL>>>(gmid, wh, wl, b_out, out);
}